// round 14
// baseline (speedup 1.0000x reference)
#include <cuda_runtime.h>
#include <cuda_fp16.h>
#include <cstdint>

#define BB 4096
#define II 256
#define OO 256
#define EE 8
#define NRB 128         // router blocks
#define ROWS_PB 32      // rows per router block
#define TSTRIDE 18

// ---------------------------------------------------------------------------
// Device scratch (no allocations allowed). NO persistent state: every launch
// overwrites all of g_blkcnt and the used prefix of g_rowlist (plain stores,
// no atomics, nothing to reset) -> replay-safe by construction.
// ---------------------------------------------------------------------------
__device__ __align__(16) int g_blkcnt[EE * NRB];            // [e*128 + b]
__device__ int g_rowlist[EE * NRB * ROWS_PB];               // [(e*128+b)*32 + j]
__device__ __half g_xh[BB * II];
__device__ __half g_xl[BB * II];
__device__ __half g_wh[EE * OO * II];                        // transposed: [e][o][i]

__device__ __forceinline__ uint32_t smem_to_u32(const void* p) {
    uint32_t a;
    asm("{ .reg .u64 t; cvta.to.shared.u64 t, %1; cvt.u32.u64 %0, t; }" : "=r"(a) : "l"(p));
    return a;
}
__device__ __forceinline__ void cp16(uint32_t dst, const void* src) {
    asm volatile("cp.async.cg.shared.global [%0], [%1], 16;" :: "r"(dst), "l"(src));
}
// D += A*B, m16n8k16 fp16 -> f32
#define MMAF16(d, a, b) \
    asm volatile( \
        "mma.sync.aligned.m16n8k16.row.col.f32.f16.f16.f32 " \
        "{%0,%1,%2,%3}, {%4,%5,%6,%7}, {%8,%9}, {%0,%1,%2,%3};" \
        : "+f"((d)[0]), "+f"((d)[1]), "+f"((d)[2]), "+f"((d)[3]) \
        : "r"((a)[0]), "r"((a)[1]), "r"((a)[2]), "r"((a)[3]), \
          "r"((b)[0]), "r"((b)[1]))
// 4-tile ldmatrix (non-transposed, b16)
#define LDSM4(r, addr) \
    asm volatile("ldmatrix.sync.aligned.m8n8.x4.shared.b16 {%0,%1,%2,%3}, [%4];" \
        : "=r"((r)[0]), "=r"((r)[1]), "=r"((r)[2]), "=r"((r)[3]) : "r"(addr))

__device__ __forceinline__ unsigned pkh(__half a, __half b) {
    __half2 t(a, b);
    return *reinterpret_cast<unsigned*>(&t);
}
__device__ __forceinline__ void splith4(float4 v, uint2& h, uint2& l) {
    __half h0 = __float2half_rn(v.x), h1 = __float2half_rn(v.y);
    __half h2 = __float2half_rn(v.z), h3 = __float2half_rn(v.w);
    __half l0 = __float2half_rn(v.x - __half2float(h0));
    __half l1 = __float2half_rn(v.y - __half2float(h1));
    __half l2 = __float2half_rn(v.z - __half2float(h2));
    __half l3 = __float2half_rn(v.w - __half2float(h3));
    h.x = pkh(h0, h1); h.y = pkh(h2, h3);
    l.x = pkh(l0, l1); l.y = pkh(l2, l3);
}

// ---------------------------------------------------------------------------
// Prep: 192 blocks, all parallel (validated R13).
// Blocks 0..127: router, 32 rows each (+x fp16 split).
// Blocks 128..191: W fp16 convert+transpose, ONE (e, o-slice) unit each.
// ---------------------------------------------------------------------------
__global__ __launch_bounds__(256) void prep_kernel(const float* __restrict__ x,
                                                   const float* __restrict__ W,
                                                   const float* __restrict__ Wp,
                                                   const float* __restrict__ bp,
                                                   float* __restrict__ y) {
    __shared__ float s_wp[EE * II];          // 8KB
    __shared__ float s_bp[EE];
    __shared__ int s_cnt[EE];
    __shared__ int s_list[EE][ROWS_PB];      // 1KB
    __shared__ float s_t[256][33];           // 33.8KB (W path)

    int tid = threadIdx.x;
    int bx = blockIdx.x;

    if (bx >= NRB) {
        // ---- W conversion: W[e][i][o] fp32 -> g_wh [e][o][i] fp16 ----
        int s = bx - NRB;                    // 0..63
        int e = s >> 3;
        int o0 = (s & 7) * 32;
        const float* wb = W + (size_t)e * II * OO;
#pragma unroll
        for (int j = 0; j < 8; j++) {
            float4 v = *reinterpret_cast<const float4*>(&wb[(size_t)tid * OO + o0 + j * 4]);
            s_t[tid][j * 4 + 0] = v.x; s_t[tid][j * 4 + 1] = v.y;
            s_t[tid][j * 4 + 2] = v.z; s_t[tid][j * 4 + 3] = v.w;
        }
        __syncthreads();
        int ol = tid >> 3;                   // 0..31 -> out row o0+ol
        int i0 = (tid & 7) * 32;             // 32 consecutive i
        unsigned hp[16];
#pragma unroll
        for (int j = 0; j < 16; j++) {
            float a = s_t[i0 + 2 * j][ol];
            float c = s_t[i0 + 2 * j + 1][ol];
            hp[j] = pkh(__float2half_rn(a), __float2half_rn(c));
        }
        size_t base = ((size_t)e * OO + o0 + ol) * II + i0;
        uint4* dh = reinterpret_cast<uint4*>(g_wh + base);
#pragma unroll
        for (int q = 0; q < 4; q++)
            dh[q] = make_uint4(hp[q * 4], hp[q * 4 + 1], hp[q * 4 + 2], hp[q * 4 + 3]);
        return;
    }

    // ---- Router (validated logic, 32 rows/block) + x fp16 split ----
    {
        const float4* Wp4 = reinterpret_cast<const float4*>(Wp);
        float4* swp4 = reinterpret_cast<float4*>(s_wp);
#pragma unroll
        for (int i = 0; i < 2; i++) swp4[tid + 256 * i] = Wp4[tid + 256 * i];
    }
    if (tid < EE) { s_bp[tid] = bp[tid]; s_cnt[tid] = 0; }
    __syncthreads();

    int warp = tid >> 5;
    int lane = tid & 31;
    int e_lane = lane >> 2;
    const float4* X4 = reinterpret_cast<const float4*>(x);
    float4* Y4 = reinterpret_cast<float4*>(y);

#pragma unroll 2
    for (int i = 0; i < 4; i++) {
        int row = bx * ROWS_PB + warp * 4 + i;
        float4 xa = X4[row * 64 + lane];
        float4 xb = X4[row * 64 + 32 + lane];

        {   // emit fp16 hi/lo split of x
            uint2 ha, la, hb, lb;
            splith4(xa, ha, la);
            splith4(xb, hb, lb);
            *reinterpret_cast<uint2*>(g_xh + (size_t)row * II + lane * 4) = ha;
            *reinterpret_cast<uint2*>(g_xl + (size_t)row * II + lane * 4) = la;
            *reinterpret_cast<uint2*>(g_xh + (size_t)row * II + 128 + lane * 4) = hb;
            *reinterpret_cast<uint2*>(g_xl + (size_t)row * II + 128 + lane * 4) = lb;
        }

        float p[EE];
#pragma unroll
        for (int e = 0; e < EE; e++) {
            const float4* we = reinterpret_cast<const float4*>(s_wp + e * II);
            float4 wa = we[lane];
            float4 wb2 = we[32 + lane];
            p[e] = xa.x * wa.x + xa.y * wa.y + xa.z * wa.z + xa.w * wa.w
                 + xb.x * wb2.x + xb.y * wb2.y + xb.z * wb2.z + xb.w * wb2.w;
        }
#pragma unroll
        for (int s = 16; s >= 4; s >>= 1)
#pragma unroll
            for (int e = 0; e < EE; e++)
                p[e] += __shfl_xor_sync(0xffffffffu, p[e], s);
        float v = p[0];
#pragma unroll
        for (int j = 1; j < EE; j++) v = (e_lane == j) ? p[j] : v;
        v += __shfl_xor_sync(0xffffffffu, v, 1);
        v += __shfl_xor_sync(0xffffffffu, v, 2);

        float z = v + s_bp[e_lane];
        float g = 1.0f / (1.0f + expf(-z));

        float m = g;
        m = fmaxf(m, __shfl_xor_sync(0xffffffffu, m, 4));
        m = fmaxf(m, __shfl_xor_sync(0xffffffffu, m, 8));
        m = fmaxf(m, __shfl_xor_sync(0xffffffffu, m, 16));

        unsigned bal = __ballot_sync(0xffffffffu, g == m);
        int nsel = __popc(bal & 0x11111111u);

        if ((g == m) && ((lane & 3) == 0)) {
            int pos = atomicAdd(&s_cnt[e_lane], 1);    // smem atomic only
            s_list[e_lane][pos] = row | (nsel > 1 ? 0x40000000 : 0);
        }
        if (nsel > 1) {     // tied rows summed via gmem atomicAdd in gemm
            Y4[row * 64 + lane] = make_float4(0.f, 0.f, 0.f, 0.f);
            Y4[row * 64 + 32 + lane] = make_float4(0.f, 0.f, 0.f, 0.f);
        }
    }
    __syncthreads();

    // Plain stores: all 8 counts per block written every launch.
    if (tid < EE) g_blkcnt[tid * NRB + bx] = s_cnt[tid];
    if (warp < EE) {
        int n = s_cnt[warp];
        if (lane < n)
            g_rowlist[(warp * NRB + bx) * ROWS_PB + lane] = s_list[warp][lane];
    }
}

// ---------------------------------------------------------------------------
// mma.sync GEMM, fp16 2-term: y = (xh + xl) * wh.
// Tile = 32 gathered rows x 128 cols, 2 CTAs/SM (validated R13).
// NEW: ldmatrix.x4 fragment loads (5 LDSM/ks vs 20 LDS.32) + register
// double-buffered ks pipeline (frags for ks+1 loaded during ks MMAs).
// grid (16, 18) = 288 blocks; K in 4 chunks of 64, triple-buffered cp.async.
// ---------------------------------------------------------------------------
#define AP 72                        // padded row stride (halfs): 144B
#define ABYTES (32 * AP * 2)         // 4608
#define BBY (128 * AP * 2)           // 18432
#define CHUNKB (2 * ABYTES + BBY)    // 27648: Ah | Al | Bh
#define SM_HDR 1024
#define SMEM_GEMM (SM_HDR + 3 * CHUNKB)     // 83968 -> 2 CTAs/SM

__global__ __launch_bounds__(256, 2) void gemm_kernel(float* __restrict__ y) {
    extern __shared__ char smem[];
    int tid = threadIdx.x, wid = tid >> 5, lane = tid & 31;
    int gid = lane >> 2, tig = lane & 3;
    int e = blockIdx.x >> 1, half = blockIdx.x & 1;
    int t0 = blockIdx.y;

    int* rowids = reinterpret_cast<int*>(smem);          // 32 ints
    int* s_p = reinterpret_cast<int*>(smem + 256);       // 129 ints

    // Prefix scan over the 128 per-block counts of expert e.
    if (tid < 32) {
        int4 v = reinterpret_cast<const int4*>(g_blkcnt + e * NRB)[tid];
        int s = v.x + v.y + v.z + v.w;
        int inc = s;
#pragma unroll
        for (int d = 1; d < 32; d <<= 1) {
            int n = __shfl_up_sync(0xffffffffu, inc, d);
            if (lane >= d) inc += n;
        }
        int ex = inc - s;
        s_p[4 * tid + 0] = ex;
        s_p[4 * tid + 1] = ex + v.x;
        s_p[4 * tid + 2] = ex + v.x + v.y;
        s_p[4 * tid + 3] = ex + v.x + v.y + v.z;
        if (tid == 31) s_p[128] = inc;
    }
    __syncthreads();
    int count = s_p[128];

    uint32_t sb = smem_to_u32(smem);
    const __half* wh = g_wh + ((size_t)e * OO + half * 128) * II;

    // Per-lane ldmatrix byte offsets.
    // A x4 (16 rows x 16 halfs): lanes 0-15 -> rows 0-15 (k-lo 16B),
    // lanes 16-31 -> rows 0-15 (+16B k-hi). Tiles T0..T3 = frag a0..a3.
    uint32_t aoff = (uint32_t)(lane & 15) * 144u + (uint32_t)(lane >> 4) * 16u;
    // B x4 (warp's 16 n-rows x 16 halfs): T0/T1 = nt0 rows (k-lo/k-hi),
    // T2/T3 = nt1 rows. lanes: 0-7 r0-7+0B, 8-15 r0-7+16B, 16-23 r8-15+0B, 24-31 r8-15+16B.
    uint32_t boff = (uint32_t)(wid * 16 + (lane & 7) + (((lane >> 4) & 1) << 3)) * 144u
                  + (uint32_t)((lane >> 3) & 1) * 16u;

#pragma unroll 1
    for (int tile = t0; tile * 32 < count; tile += TSTRIDE) {
        __syncthreads();    // guard rowids reuse across tile iterations
        if (tid < 32) {
            int g = tile * 32 + tid;
            int rv = -1;
            if (g < count) {
                int lo = 0, hi = 128;
#pragma unroll
                for (int st = 0; st < 7; st++) {
                    int mid = (lo + hi) >> 1;
                    if (s_p[mid] <= g) lo = mid; else hi = mid;
                }
                rv = g_rowlist[(e * NRB + lo) * ROWS_PB + (g - s_p[lo])];
            }
            rowids[tid] = rv;
        }
        __syncthreads();

        int ar = tid >> 3;                       // A row 0..31
        int ac = tid & 7;                        // 16B chunk 0..7
        int rvA = rowids[ar];
        int ridA = (rvA < 0) ? 0 : (rvA & 0x3FFFFFFF);
        const __half* xh = g_xh + (size_t)ridA * II;
        const __half* xl = g_xl + (size_t)ridA * II;

        auto load_chunk = [&](int c, int b) {
            uint32_t base = sb + SM_HDR + b * CHUNKB;
            int kc = c * 64;
            uint32_t offA = ar * 144 + ac * 16;
            cp16(base + offA, xh + kc + ac * 8);
            cp16(base + ABYTES + offA, xl + kc + ac * 8);
#pragma unroll
            for (int j = 0; j < 4; j++) {
                int n = (tid >> 3) + j * 32;     // 0..127
                cp16(base + 2 * ABYTES + n * 144 + ac * 16, wh + (size_t)n * II + kc + ac * 8);
            }
            asm volatile("cp.async.commit_group;" ::: "memory");
        };

        float d[2][2][4];
#pragma unroll
        for (int mt = 0; mt < 2; mt++)
#pragma unroll
            for (int nt = 0; nt < 2; nt++)
#pragma unroll
                for (int q = 0; q < 4; q++) d[mt][nt][q] = 0.f;

        load_chunk(0, 0);
        load_chunk(1, 1);

#pragma unroll
        for (int c = 0; c < 4; c++) {
            if (c < 2) {
                load_chunk(c + 2, (c + 2) % 3);
                asm volatile("cp.async.wait_group 2;" ::: "memory");
            } else if (c == 2) {
                asm volatile("cp.async.wait_group 1;" ::: "memory");
            } else {
                asm volatile("cp.async.wait_group 0;" ::: "memory");
            }
            __syncthreads();

            uint32_t bufb = sb + SM_HDR + (c % 3) * CHUNKB;
            uint32_t aAh0 = bufb + aoff;                     // A hi rows 0-15
            uint32_t aAh1 = bufb + 2304 + aoff;              // A hi rows 16-31
            uint32_t aAl0 = bufb + ABYTES + aoff;            // A lo rows 0-15
            uint32_t aAl1 = bufb + ABYTES + 2304 + aoff;     // A lo rows 16-31
            uint32_t aB   = bufb + 2 * ABYTES + boff;        // B (warp's 16 n-rows)

            // Register double-buffered ks pipeline
            uint32_t fh[2][2][4], fl[2][2][4], fb[2][4];
            LDSM4(fh[0][0], aAh0);
            LDSM4(fh[0][1], aAh1);
            LDSM4(fl[0][0], aAl0);
            LDSM4(fl[0][1], aAl1);
            LDSM4(fb[0], aB);

#pragma unroll
            for (int ks = 0; ks < 4; ks++) {
                int cur = ks & 1, nxt = cur ^ 1;
                if (ks < 3) {
                    uint32_t o = (uint32_t)(ks + 1) * 32u;
                    LDSM4(fh[nxt][0], aAh0 + o);
                    LDSM4(fh[nxt][1], aAh1 + o);
                    LDSM4(fl[nxt][0], aAl0 + o);
                    LDSM4(fl[nxt][1], aAl1 + o);
                    LDSM4(fb[nxt], aB + o);
                }
#pragma unroll
                for (int nt = 0; nt < 2; nt++) {
#pragma unroll
                    for (int mt = 0; mt < 2; mt++) {
                        MMAF16(d[mt][nt], fh[cur][mt], fb[cur] + nt * 2);   // xh * wh
                        MMAF16(d[mt][nt], fl[cur][mt], fb[cur] + nt * 2);   // xl * wh
                    }
                }
            }
            __syncthreads();
        }

        // Epilogue: scatter D fragments (cols: half*128 + wid*16 + nt*8 + 2*tig)
#pragma unroll
        for (int mt = 0; mt < 2; mt++) {
#pragma unroll
            for (int h = 0; h < 2; h++) {
                int rr = mt * 16 + gid + h * 8;
                int rv = rowids[rr];
                if (rv < 0) continue;
                int rid = rv & 0x3FFFFFFF;
                bool multi = (rv & 0x40000000) != 0;
                float* yp = y + (size_t)rid * OO + half * 128 + wid * 16 + 2 * tig;
                if (multi) {
#pragma unroll
                    for (int nt = 0; nt < 2; nt++) {
                        atomicAdd(&yp[nt * 8], d[mt][nt][h * 2 + 0]);
                        atomicAdd(&yp[nt * 8 + 1], d[mt][nt][h * 2 + 1]);
                    }
                } else {
#pragma unroll
                    for (int nt = 0; nt < 2; nt++)
                        *reinterpret_cast<float2*>(&yp[nt * 8]) =
                            make_float2(d[mt][nt][h * 2 + 0], d[mt][nt][h * 2 + 1]);
                }
            }
        }
    }
}

extern "C" void kernel_launch(void* const* d_in, const int* in_sizes, int n_in,
                              void* d_out, int out_size) {
    const float* x  = (const float*)d_in[0];
    const float* W  = (const float*)d_in[1];
    const float* Wp = (const float*)d_in[2];
    const float* bp = (const float*)d_in[3];
    float* y = (float*)d_out;

    cudaFuncSetAttribute(gemm_kernel, cudaFuncAttributeMaxDynamicSharedMemorySize, SMEM_GEMM);
    prep_kernel<<<192, 256>>>(x, W, Wp, bp, y);
    gemm_kernel<<<dim3(16, TSTRIDE), 256, SMEM_GEMM>>>(y);
}

// round 15
// speedup vs baseline: 1.0343x; 1.0343x over previous
#include <cuda_runtime.h>
#include <cuda_fp16.h>
#include <cstdint>

#define BB 4096
#define II 256
#define OO 256
#define EE 8
#define NRB 128         // router blocks
#define ROWS_PB 32      // rows per router block
#define TSTRIDE 18

// ---------------------------------------------------------------------------
// Device scratch (no allocations allowed). NO persistent state: every launch
// overwrites all of g_blkcnt and the used prefix of g_rowlist (plain stores,
// no atomics, nothing to reset) -> replay-safe by construction.
// ---------------------------------------------------------------------------
__device__ __align__(16) int g_blkcnt[EE * NRB];            // [e*128 + b]
__device__ int g_rowlist[EE * NRB * ROWS_PB];               // [(e*128+b)*32 + j]
__device__ __half g_xh[BB * II];
__device__ __half g_xl[BB * II];
__device__ __half g_wh[EE * OO * II];                        // transposed: [e][o][i]

__device__ __forceinline__ uint32_t smem_to_u32(const void* p) {
    uint32_t a;
    asm("{ .reg .u64 t; cvta.to.shared.u64 t, %1; cvt.u32.u64 %0, t; }" : "=r"(a) : "l"(p));
    return a;
}
__device__ __forceinline__ void cp16(uint32_t dst, const void* src) {
    asm volatile("cp.async.cg.shared.global [%0], [%1], 16;" :: "r"(dst), "l"(src));
}
// D += A*B, m16n8k16 fp16 -> f32
#define MMAF16(d, a, b) \
    asm volatile( \
        "mma.sync.aligned.m16n8k16.row.col.f32.f16.f16.f32 " \
        "{%0,%1,%2,%3}, {%4,%5,%6,%7}, {%8,%9}, {%0,%1,%2,%3};" \
        : "+f"((d)[0]), "+f"((d)[1]), "+f"((d)[2]), "+f"((d)[3]) \
        : "r"((a)[0]), "r"((a)[1]), "r"((a)[2]), "r"((a)[3]), \
          "r"((b)[0]), "r"((b)[1]))
// 4-tile ldmatrix (non-transposed, b16)
#define LDSM4(r, addr) \
    asm volatile("ldmatrix.sync.aligned.m8n8.x4.shared.b16 {%0,%1,%2,%3}, [%4];" \
        : "=r"((r)[0]), "=r"((r)[1]), "=r"((r)[2]), "=r"((r)[3]) : "r"(addr))

__device__ __forceinline__ unsigned pkh(__half a, __half b) {
    __half2 t(a, b);
    return *reinterpret_cast<unsigned*>(&t);
}
__device__ __forceinline__ void splith4(float4 v, uint2& h, uint2& l) {
    __half h0 = __float2half_rn(v.x), h1 = __float2half_rn(v.y);
    __half h2 = __float2half_rn(v.z), h3 = __float2half_rn(v.w);
    __half l0 = __float2half_rn(v.x - __half2float(h0));
    __half l1 = __float2half_rn(v.y - __half2float(h1));
    __half l2 = __float2half_rn(v.z - __half2float(h2));
    __half l3 = __float2half_rn(v.w - __half2float(h3));
    h.x = pkh(h0, h1); h.y = pkh(h2, h3);
    l.x = pkh(l0, l1); l.y = pkh(l2, l3);
}

// ---------------------------------------------------------------------------
// Prep: 192 blocks, all parallel (validated R13/R14, unchanged).
// ---------------------------------------------------------------------------
__global__ __launch_bounds__(256) void prep_kernel(const float* __restrict__ x,
                                                   const float* __restrict__ W,
                                                   const float* __restrict__ Wp,
                                                   const float* __restrict__ bp,
                                                   float* __restrict__ y) {
    __shared__ float s_wp[EE * II];          // 8KB
    __shared__ float s_bp[EE];
    __shared__ int s_cnt[EE];
    __shared__ int s_list[EE][ROWS_PB];      // 1KB
    __shared__ float s_t[256][33];           // 33.8KB (W path)

    int tid = threadIdx.x;
    int bx = blockIdx.x;

    if (bx >= NRB) {
        // ---- W conversion: W[e][i][o] fp32 -> g_wh [e][o][i] fp16 ----
        int s = bx - NRB;                    // 0..63
        int e = s >> 3;
        int o0 = (s & 7) * 32;
        const float* wb = W + (size_t)e * II * OO;
#pragma unroll
        for (int j = 0; j < 8; j++) {
            float4 v = *reinterpret_cast<const float4*>(&wb[(size_t)tid * OO + o0 + j * 4]);
            s_t[tid][j * 4 + 0] = v.x; s_t[tid][j * 4 + 1] = v.y;
            s_t[tid][j * 4 + 2] = v.z; s_t[tid][j * 4 + 3] = v.w;
        }
        __syncthreads();
        int ol = tid >> 3;                   // 0..31 -> out row o0+ol
        int i0 = (tid & 7) * 32;             // 32 consecutive i
        unsigned hp[16];
#pragma unroll
        for (int j = 0; j < 16; j++) {
            float a = s_t[i0 + 2 * j][ol];
            float c = s_t[i0 + 2 * j + 1][ol];
            hp[j] = pkh(__float2half_rn(a), __float2half_rn(c));
        }
        size_t base = ((size_t)e * OO + o0 + ol) * II + i0;
        uint4* dh = reinterpret_cast<uint4*>(g_wh + base);
#pragma unroll
        for (int q = 0; q < 4; q++)
            dh[q] = make_uint4(hp[q * 4], hp[q * 4 + 1], hp[q * 4 + 2], hp[q * 4 + 3]);
        return;
    }

    // ---- Router (validated logic, 32 rows/block) + x fp16 split ----
    {
        const float4* Wp4 = reinterpret_cast<const float4*>(Wp);
        float4* swp4 = reinterpret_cast<float4*>(s_wp);
#pragma unroll
        for (int i = 0; i < 2; i++) swp4[tid + 256 * i] = Wp4[tid + 256 * i];
    }
    if (tid < EE) { s_bp[tid] = bp[tid]; s_cnt[tid] = 0; }
    __syncthreads();

    int warp = tid >> 5;
    int lane = tid & 31;
    int e_lane = lane >> 2;
    const float4* X4 = reinterpret_cast<const float4*>(x);
    float4* Y4 = reinterpret_cast<float4*>(y);

#pragma unroll 2
    for (int i = 0; i < 4; i++) {
        int row = bx * ROWS_PB + warp * 4 + i;
        float4 xa = X4[row * 64 + lane];
        float4 xb = X4[row * 64 + 32 + lane];

        {   // emit fp16 hi/lo split of x
            uint2 ha, la, hb, lb;
            splith4(xa, ha, la);
            splith4(xb, hb, lb);
            *reinterpret_cast<uint2*>(g_xh + (size_t)row * II + lane * 4) = ha;
            *reinterpret_cast<uint2*>(g_xl + (size_t)row * II + lane * 4) = la;
            *reinterpret_cast<uint2*>(g_xh + (size_t)row * II + 128 + lane * 4) = hb;
            *reinterpret_cast<uint2*>(g_xl + (size_t)row * II + 128 + lane * 4) = lb;
        }

        float p[EE];
#pragma unroll
        for (int e = 0; e < EE; e++) {
            const float4* we = reinterpret_cast<const float4*>(s_wp + e * II);
            float4 wa = we[lane];
            float4 wb2 = we[32 + lane];
            p[e] = xa.x * wa.x + xa.y * wa.y + xa.z * wa.z + xa.w * wa.w
                 + xb.x * wb2.x + xb.y * wb2.y + xb.z * wb2.z + xb.w * wb2.w;
        }
#pragma unroll
        for (int s = 16; s >= 4; s >>= 1)
#pragma unroll
            for (int e = 0; e < EE; e++)
                p[e] += __shfl_xor_sync(0xffffffffu, p[e], s);
        float v = p[0];
#pragma unroll
        for (int j = 1; j < EE; j++) v = (e_lane == j) ? p[j] : v;
        v += __shfl_xor_sync(0xffffffffu, v, 1);
        v += __shfl_xor_sync(0xffffffffu, v, 2);

        float z = v + s_bp[e_lane];
        float g = 1.0f / (1.0f + expf(-z));

        float m = g;
        m = fmaxf(m, __shfl_xor_sync(0xffffffffu, m, 4));
        m = fmaxf(m, __shfl_xor_sync(0xffffffffu, m, 8));
        m = fmaxf(m, __shfl_xor_sync(0xffffffffu, m, 16));

        unsigned bal = __ballot_sync(0xffffffffu, g == m);
        int nsel = __popc(bal & 0x11111111u);

        if ((g == m) && ((lane & 3) == 0)) {
            int pos = atomicAdd(&s_cnt[e_lane], 1);    // smem atomic only
            s_list[e_lane][pos] = row | (nsel > 1 ? 0x40000000 : 0);
        }
        if (nsel > 1) {     // tied rows summed via gmem atomicAdd in gemm
            Y4[row * 64 + lane] = make_float4(0.f, 0.f, 0.f, 0.f);
            Y4[row * 64 + 32 + lane] = make_float4(0.f, 0.f, 0.f, 0.f);
        }
    }
    __syncthreads();

    // Plain stores: all 8 counts per block written every launch.
    if (tid < EE) g_blkcnt[tid * NRB + bx] = s_cnt[tid];
    if (warp < EE) {
        int n = s_cnt[warp];
        if (lane < n)
            g_rowlist[(warp * NRB + bx) * ROWS_PB + lane] = s_list[warp][lane];
    }
}

// ---------------------------------------------------------------------------
// mma.sync GEMM, fp16 2-term: y = (xh + xl) * wh.
// NEW structure: the WHOLE B half-tile (4 sections, 72KB) is cp.async'd at
// block start (before the routing scan -> scan latency hidden), and all 4 A
// chunks are issued right after rowids. 8 commit groups total; chunk c gates
// on wait_group(3-c) + ONE bar.sync. No per-chunk loads, no double buffering,
// no trailing barriers -> 4 nearly-continuous compute phases.
// Tile = 32 gathered rows x 128 cols; smem 109KB -> still 2 CTAs/SM.
// grid (16, 18) = 288 blocks; ldmatrix frag loads (validated R14).
// ---------------------------------------------------------------------------
#define AP 72                        // padded row stride (halfs): 144B
#define ASEC 9216                    // per-chunk A section: Ah[32][72]+Al[32][72]
#define BSEC 18432                   // per-chunk B section: 128 x 72 halfs
#define SM_B 1024
#define SM_A (SM_B + 4 * BSEC)       // 74752
#define SMEM_GEMM (SM_A + 4 * ASEC)  // 111616 -> 2 CTAs/SM (223KB/SM)

__global__ __launch_bounds__(256, 2) void gemm_kernel(float* __restrict__ y) {
    extern __shared__ char smem[];
    int tid = threadIdx.x, wid = tid >> 5, lane = tid & 31;
    int gid = lane >> 2, tig = lane & 3;
    int e = blockIdx.x >> 1, half = blockIdx.x & 1;
    int t0 = blockIdx.y;

    int* rowids = reinterpret_cast<int*>(smem);          // 32 ints
    int* s_p = reinterpret_cast<int*>(smem + 256);       // 129 ints

    uint32_t sb = smem_to_u32(smem);
    const __half* wh = g_wh + ((size_t)e * OO + half * 128) * II;
    int ac = tid & 7;                        // 16B chunk 0..7 (loader role)

    // ---- Issue ALL B loads first (no routing dependency): 4 commit groups.
#pragma unroll
    for (int c = 0; c < 4; c++) {
#pragma unroll
        for (int j = 0; j < 4; j++) {
            int n = (tid >> 3) + j * 32;     // 0..127
            cp16(sb + SM_B + c * BSEC + n * 144 + ac * 16,
                 wh + (size_t)n * II + c * 64 + ac * 8);
        }
        asm volatile("cp.async.commit_group;" ::: "memory");
    }

    // ---- Routing scan (overlaps with B transfer in flight) ----
    if (tid < 32) {
        int4 v = reinterpret_cast<const int4*>(g_blkcnt + e * NRB)[tid];
        int s = v.x + v.y + v.z + v.w;
        int inc = s;
#pragma unroll
        for (int d = 1; d < 32; d <<= 1) {
            int n = __shfl_up_sync(0xffffffffu, inc, d);
            if (lane >= d) inc += n;
        }
        int ex = inc - s;
        s_p[4 * tid + 0] = ex;
        s_p[4 * tid + 1] = ex + v.x;
        s_p[4 * tid + 2] = ex + v.x + v.y;
        s_p[4 * tid + 3] = ex + v.x + v.y + v.z;
        if (tid == 31) s_p[128] = inc;
    }
    __syncthreads();
    int count = s_p[128];

    if (t0 * 32 >= count) {
        // Idle block: drain pending cp.async groups before exit.
        asm volatile("cp.async.wait_group 0;" ::: "memory");
        return;
    }

    // ldmatrix per-lane byte offsets (validated R14 mapping).
    uint32_t aoff = (uint32_t)(lane & 15) * 144u + (uint32_t)(lane >> 4) * 16u;
    uint32_t boff = (uint32_t)(wid * 16 + (lane & 7) + (((lane >> 4) & 1) << 3)) * 144u
                  + (uint32_t)((lane >> 3) & 1) * 16u;

#pragma unroll 1
    for (int tile = t0; tile * 32 < count; tile += TSTRIDE) {
        if (tid < 32) {
            int g = tile * 32 + tid;
            int rv = -1;
            if (g < count) {
                int lo = 0, hi = 128;
#pragma unroll
                for (int st = 0; st < 7; st++) {
                    int mid = (lo + hi) >> 1;
                    if (s_p[mid] <= g) lo = mid; else hi = mid;
                }
                rv = g_rowlist[(e * NRB + lo) * ROWS_PB + (g - s_p[lo])];
            }
            rowids[tid] = rv;
        }
        __syncthreads();

        int ar = tid >> 3;                       // A row 0..31
        int rvA = rowids[ar];
        int ridA = (rvA < 0) ? 0 : (rvA & 0x3FFFFFFF);
        const __half* xh = g_xh + (size_t)ridA * II;
        const __half* xl = g_xl + (size_t)ridA * II;

        // ---- Issue ALL A chunk loads: 4 more commit groups ----
#pragma unroll
        for (int c = 0; c < 4; c++) {
            uint32_t offA = sb + SM_A + c * ASEC + ar * 144 + ac * 16;
            cp16(offA, xh + c * 64 + ac * 8);
            cp16(offA + 4608, xl + c * 64 + ac * 8);
            asm volatile("cp.async.commit_group;" ::: "memory");
        }

        float d[2][2][4];
#pragma unroll
        for (int mt = 0; mt < 2; mt++)
#pragma unroll
            for (int nt = 0; nt < 2; nt++)
#pragma unroll
                for (int q = 0; q < 4; q++) d[mt][nt][q] = 0.f;

#pragma unroll
        for (int c = 0; c < 4; c++) {
            // Gate: B section c (group c) + A chunk c (group 4+c) complete.
            if (c == 0)      asm volatile("cp.async.wait_group 3;" ::: "memory");
            else if (c == 1) asm volatile("cp.async.wait_group 2;" ::: "memory");
            else if (c == 2) asm volatile("cp.async.wait_group 1;" ::: "memory");
            else             asm volatile("cp.async.wait_group 0;" ::: "memory");
            __syncthreads();

            uint32_t abase = sb + SM_A + c * ASEC;
            uint32_t aAh0 = abase + aoff;                    // A hi rows 0-15
            uint32_t aAh1 = abase + 2304 + aoff;             // A hi rows 16-31
            uint32_t aAl0 = abase + 4608 + aoff;             // A lo rows 0-15
            uint32_t aAl1 = abase + 4608 + 2304 + aoff;      // A lo rows 16-31
            uint32_t aB   = sb + SM_B + c * BSEC + boff;     // B (warp's 16 n-rows)

            // Register double-buffered ks pipeline
            uint32_t fh[2][2][4], fl[2][2][4], fb[2][4];
            LDSM4(fh[0][0], aAh0);
            LDSM4(fh[0][1], aAh1);
            LDSM4(fl[0][0], aAl0);
            LDSM4(fl[0][1], aAl1);
            LDSM4(fb[0], aB);

#pragma unroll
            for (int ks = 0; ks < 4; ks++) {
                int cur = ks & 1, nxt = cur ^ 1;
                if (ks < 3) {
                    uint32_t o = (uint32_t)(ks + 1) * 32u;
                    LDSM4(fh[nxt][0], aAh0 + o);
                    LDSM4(fh[nxt][1], aAh1 + o);
                    LDSM4(fl[nxt][0], aAl0 + o);
                    LDSM4(fl[nxt][1], aAl1 + o);
                    LDSM4(fb[nxt], aB + o);
                }
#pragma unroll
                for (int nt = 0; nt < 2; nt++) {
#pragma unroll
                    for (int mt = 0; mt < 2; mt++) {
                        MMAF16(d[mt][nt], fh[cur][mt], fb[cur] + nt * 2);   // xh * wh
                        MMAF16(d[mt][nt], fl[cur][mt], fb[cur] + nt * 2);   // xl * wh
                    }
                }
            }
            // no trailing barrier: smem is read-only until the tile loop wraps
        }

        // Epilogue: scatter D fragments (cols: half*128 + wid*16 + nt*8 + 2*tig)
#pragma unroll
        for (int mt = 0; mt < 2; mt++) {
#pragma unroll
            for (int h = 0; h < 2; h++) {
                int rr = mt * 16 + gid + h * 8;
                int rv = rowids[rr];
                if (rv < 0) continue;
                int rid = rv & 0x3FFFFFFF;
                bool multi = (rv & 0x40000000) != 0;
                float* yp = y + (size_t)rid * OO + half * 128 + wid * 16 + 2 * tig;
                if (multi) {
#pragma unroll
                    for (int nt = 0; nt < 2; nt++) {
                        atomicAdd(&yp[nt * 8], d[mt][nt][h * 2 + 0]);
                        atomicAdd(&yp[nt * 8 + 1], d[mt][nt][h * 2 + 1]);
                    }
                } else {
#pragma unroll
                    for (int nt = 0; nt < 2; nt++)
                        *reinterpret_cast<float2*>(&yp[nt * 8]) =
                            make_float2(d[mt][nt][h * 2 + 0], d[mt][nt][h * 2 + 1]);
                }
            }
        }
        __syncthreads();    // all reads of rowids/A sections done before next tile rewrites
    }
}

extern "C" void kernel_launch(void* const* d_in, const int* in_sizes, int n_in,
                              void* d_out, int out_size) {
    const float* x  = (const float*)d_in[0];
    const float* W  = (const float*)d_in[1];
    const float* Wp = (const float*)d_in[2];
    const float* bp = (const float*)d_in[3];
    float* y = (float*)d_out;

    cudaFuncSetAttribute(gemm_kernel, cudaFuncAttributeMaxDynamicSharedMemorySize, SMEM_GEMM);
    prep_kernel<<<192, 256>>>(x, W, Wp, bp, y);
    gemm_kernel<<<dim3(16, TSTRIDE), 256, SMEM_GEMM>>>(y);
}

// round 17
// speedup vs baseline: 1.1218x; 1.0846x over previous
#include <cuda_runtime.h>
#include <cuda_fp16.h>
#include <cstdint>

#define BB 4096
#define II 256
#define OO 256
#define EE 8
#define NRB 128         // router blocks
#define ROWS_PB 32      // rows per router block
#define TSTRIDE 18

// ---------------------------------------------------------------------------
// Device scratch (no allocations allowed). NO persistent state: every launch
// overwrites all of g_blkcnt and the used prefix of g_rowlist (plain stores,
// no atomics, nothing to reset) -> replay-safe by construction.
// ---------------------------------------------------------------------------
__device__ __align__(16) int g_blkcnt[EE * NRB];            // [e*128 + b]
__device__ int g_rowlist[EE * NRB * ROWS_PB];               // [(e*128+b)*32 + j]
__device__ __half g_xh[BB * II];                             // x in fp16
__device__ __half g_wh[EE * OO * II];                        // transposed: [e][o][i]

__device__ __forceinline__ uint32_t smem_to_u32(const void* p) {
    uint32_t a;
    asm("{ .reg .u64 t; cvta.to.shared.u64 t, %1; cvt.u32.u64 %0, t; }" : "=r"(a) : "l"(p));
    return a;
}
__device__ __forceinline__ void cp16(uint32_t dst, const void* src) {
    asm volatile("cp.async.cg.shared.global [%0], [%1], 16;" :: "r"(dst), "l"(src));
}
// D += A*B, m16n8k16 fp16 -> f32
#define MMAF16(d, a, b) \
    asm volatile( \
        "mma.sync.aligned.m16n8k16.row.col.f32.f16.f16.f32 " \
        "{%0,%1,%2,%3}, {%4,%5,%6,%7}, {%8,%9}, {%0,%1,%2,%3};" \
        : "+f"((d)[0]), "+f"((d)[1]), "+f"((d)[2]), "+f"((d)[3]) \
        : "r"((a)[0]), "r"((a)[1]), "r"((a)[2]), "r"((a)[3]), \
          "r"((b)[0]), "r"((b)[1]))
// 4-tile ldmatrix (non-transposed, b16)
#define LDSM4(r, addr) \
    asm volatile("ldmatrix.sync.aligned.m8n8.x4.shared.b16 {%0,%1,%2,%3}, [%4];" \
        : "=r"((r)[0]), "=r"((r)[1]), "=r"((r)[2]), "=r"((r)[3]) : "r"(addr))

__device__ __forceinline__ unsigned pkh(__half a, __half b) {
    __half2 t(a, b);
    return *reinterpret_cast<unsigned*>(&t);
}
__device__ __forceinline__ uint2 cvt4(float4 v) {
    uint2 h;
    h.x = pkh(__float2half_rn(v.x), __float2half_rn(v.y));
    h.y = pkh(__float2half_rn(v.z), __float2half_rn(v.w));
    return h;
}

// ---------------------------------------------------------------------------
// Prep: 128 blocks -> ONE wave. Every block routes 32 rows (+x fp16 convert).
// Blocks 0..63 ADDITIONALLY convert one W (e, o-slice) unit; its 32KB W read
// is cp.async'd BEFORE the router section so it lands under router compute.
// All counts/rows written with plain stores.
// ---------------------------------------------------------------------------
__global__ __launch_bounds__(256) void prep_kernel(const float* __restrict__ x,
                                                   const float* __restrict__ W,
                                                   const float* __restrict__ Wp,
                                                   const float* __restrict__ bp,
                                                   float* __restrict__ y) {
    __shared__ float s_wp[EE * II];          // 8KB
    __shared__ float s_bp[EE];
    __shared__ int s_cnt[EE];
    __shared__ int s_list[EE][ROWS_PB];      // 1KB
    __shared__ float s_t[256][36];           // 36KB (W path, 144B rows for cp16)

    int tid = threadIdx.x;
    int bx = blockIdx.x;
    bool has_w = (bx < 64);

    // ---- Issue W slice read early (async, overlaps router compute) ----
    if (has_w) {
        int e = bx >> 3;
        int o0 = (bx & 7) * 32;
        const float* wb = W + (size_t)e * II * OO + o0;
        uint32_t st = smem_to_u32(&s_t[0][0]) + (uint32_t)tid * 144u;
#pragma unroll
        for (int j = 0; j < 8; j++)
            cp16(st + j * 16, wb + (size_t)tid * OO + j * 4);
        asm volatile("cp.async.commit_group;" ::: "memory");
    }

    // ---- Router (validated logic, 32 rows/block) + x fp16 convert ----
    {
        const float4* Wp4 = reinterpret_cast<const float4*>(Wp);
        float4* swp4 = reinterpret_cast<float4*>(s_wp);
#pragma unroll
        for (int i = 0; i < 2; i++) swp4[tid + 256 * i] = Wp4[tid + 256 * i];
    }
    if (tid < EE) { s_bp[tid] = bp[tid]; s_cnt[tid] = 0; }
    __syncthreads();

    int warp = tid >> 5;
    int lane = tid & 31;
    int e_lane = lane >> 2;
    const float4* X4 = reinterpret_cast<const float4*>(x);
    float4* Y4 = reinterpret_cast<float4*>(y);

#pragma unroll 2
    for (int i = 0; i < 4; i++) {
        int row = bx * ROWS_PB + warp * 4 + i;
        float4 xa = X4[row * 64 + lane];
        float4 xb = X4[row * 64 + 32 + lane];

        // emit fp16 x
        *reinterpret_cast<uint2*>(g_xh + (size_t)row * II + lane * 4) = cvt4(xa);
        *reinterpret_cast<uint2*>(g_xh + (size_t)row * II + 128 + lane * 4) = cvt4(xb);

        float p[EE];
#pragma unroll
        for (int e = 0; e < EE; e++) {
            const float4* we = reinterpret_cast<const float4*>(s_wp + e * II);
            float4 wa = we[lane];
            float4 wb2 = we[32 + lane];
            p[e] = xa.x * wa.x + xa.y * wa.y + xa.z * wa.z + xa.w * wa.w
                 + xb.x * wb2.x + xb.y * wb2.y + xb.z * wb2.z + xb.w * wb2.w;
        }
#pragma unroll
        for (int s = 16; s >= 4; s >>= 1)
#pragma unroll
            for (int e = 0; e < EE; e++)
                p[e] += __shfl_xor_sync(0xffffffffu, p[e], s);
        float v = p[0];
#pragma unroll
        for (int j = 1; j < EE; j++) v = (e_lane == j) ? p[j] : v;
        v += __shfl_xor_sync(0xffffffffu, v, 1);
        v += __shfl_xor_sync(0xffffffffu, v, 2);

        float z = v + s_bp[e_lane];
        float g = 1.0f / (1.0f + expf(-z));

        float m = g;
        m = fmaxf(m, __shfl_xor_sync(0xffffffffu, m, 4));
        m = fmaxf(m, __shfl_xor_sync(0xffffffffu, m, 8));
        m = fmaxf(m, __shfl_xor_sync(0xffffffffu, m, 16));

        unsigned bal = __ballot_sync(0xffffffffu, g == m);
        int nsel = __popc(bal & 0x11111111u);

        if ((g == m) && ((lane & 3) == 0)) {
            int pos = atomicAdd(&s_cnt[e_lane], 1);    // smem atomic only
            s_list[e_lane][pos] = row | (nsel > 1 ? 0x40000000 : 0);
        }
        if (nsel > 1) {     // tied rows summed via gmem atomicAdd in gemm
            Y4[row * 64 + lane] = make_float4(0.f, 0.f, 0.f, 0.f);
            Y4[row * 64 + 32 + lane] = make_float4(0.f, 0.f, 0.f, 0.f);
        }
    }
    __syncthreads();

    // Plain stores: all 8 counts per block written every launch.
    if (tid < EE) g_blkcnt[tid * NRB + bx] = s_cnt[tid];
    if (warp < EE) {
        int n = s_cnt[warp];
        if (lane < n)
            g_rowlist[(warp * NRB + bx) * ROWS_PB + lane] = s_list[warp][lane];
    }

    // ---- W transpose/convert (data arrived during router) ----
    if (has_w) {
        asm volatile("cp.async.wait_group 0;" ::: "memory");
        __syncthreads();
        int e = bx >> 3;
        int o0 = (bx & 7) * 32;
        int ol = tid >> 3;                   // 0..31 -> out row o0+ol
        int i0 = (tid & 7) * 32;             // 32 consecutive i
        unsigned hp[16];
#pragma unroll
        for (int j = 0; j < 16; j++) {
            float a = s_t[i0 + 2 * j][ol];
            float c = s_t[i0 + 2 * j + 1][ol];
            hp[j] = pkh(__float2half_rn(a), __float2half_rn(c));
        }
        size_t base = ((size_t)e * OO + o0 + ol) * II + i0;
        uint4* dh = reinterpret_cast<uint4*>(g_wh + base);
#pragma unroll
        for (int q = 0; q < 4; q++)
            dh[q] = make_uint4(hp[q * 4], hp[q * 4 + 1], hp[q * 4 + 2], hp[q * 4 + 3]);
    }
}

// ---------------------------------------------------------------------------
// mma.sync GEMM, single-term fp16: y = xh * wh (x,W both fp16-rounded).
// Tile = 32 gathered rows x 128 cols, 2 CTAs/SM. grid (16, 18) = 288 blocks.
// COMMIT-ORDER FIX: groups complete in order, so commits are interleaved
// B0 | (scan) | A0,B1,A1,B2,A2,B3,A3 -> chunk 0 gates on just B0+A0 (23KB),
// not the whole B transfer. ks-parity-split accumulators (serial HMMA chain
// 16 -> 8). ldmatrix frag loads + register ks pipeline (validated).
// ---------------------------------------------------------------------------
#define AP 72                        // padded row stride (halfs): 144B
#define ASEC 4608                    // per-chunk A section: 32 x 72 halfs
#define BSEC 18432                   // per-chunk B section: 128 x 72 halfs
#define SM_B 1024
#define SM_A (SM_B + 4 * BSEC)       // 74752
#define SMEM_GEMM (SM_A + 4 * ASEC)  // 93184 -> 2 CTAs/SM

__global__ __launch_bounds__(256, 2) void gemm_kernel(float* __restrict__ y) {
    extern __shared__ char smem[];
    int tid = threadIdx.x, wid = tid >> 5, lane = tid & 31;
    int gid = lane >> 2, tig = lane & 3;
    int e = blockIdx.x >> 1, half = blockIdx.x & 1;
    int t0 = blockIdx.y;

    int* rowids = reinterpret_cast<int*>(smem);          // 32 ints
    int* s_p = reinterpret_cast<int*>(smem + 256);       // 129 ints

    uint32_t sb = smem_to_u32(smem);
    const __half* wh = g_wh + ((size_t)e * OO + half * 128) * II;
    int ac = tid & 7;                        // 16B chunk 0..7 (loader role)

    auto loadB = [&](int c) {
#pragma unroll
        for (int j = 0; j < 4; j++) {
            int n = (tid >> 3) + j * 32;     // 0..127
            cp16(sb + SM_B + c * BSEC + n * 144 + ac * 16,
                 wh + (size_t)n * II + c * 64 + ac * 8);
        }
        asm volatile("cp.async.commit_group;" ::: "memory");
    };

    // ---- group 0: B chunk 0 only (covers scan latency) ----
    loadB(0);

    // ---- Routing scan (overlaps with B0 transfer) ----
    if (tid < 32) {
        int4 v = reinterpret_cast<const int4*>(g_blkcnt + e * NRB)[tid];
        int s = v.x + v.y + v.z + v.w;
        int inc = s;
#pragma unroll
        for (int d = 1; d < 32; d <<= 1) {
            int n = __shfl_up_sync(0xffffffffu, inc, d);
            if (lane >= d) inc += n;
        }
        int ex = inc - s;
        s_p[4 * tid + 0] = ex;
        s_p[4 * tid + 1] = ex + v.x;
        s_p[4 * tid + 2] = ex + v.x + v.y;
        s_p[4 * tid + 3] = ex + v.x + v.y + v.z;
        if (tid == 31) s_p[128] = inc;
    }
    __syncthreads();
    int count = s_p[128];

    if (t0 * 32 >= count) {
        asm volatile("cp.async.wait_group 0;" ::: "memory");  // drain B0
        return;
    }

    // ldmatrix per-lane byte offsets (validated mapping).
    uint32_t aoff = (uint32_t)(lane & 15) * 144u + (uint32_t)(lane >> 4) * 16u;
    uint32_t boff = (uint32_t)(wid * 16 + (lane & 7) + (((lane >> 4) & 1) << 3)) * 144u
                  + (uint32_t)((lane >> 3) & 1) * 16u;

    bool first_tile = true;
#pragma unroll 1
    for (int tile = t0; tile * 32 < count; tile += TSTRIDE) {
        if (tid < 32) {
            int g = tile * 32 + tid;
            int rv = -1;
            if (g < count) {
                int lo = 0, hi = 128;
#pragma unroll
                for (int st = 0; st < 7; st++) {
                    int mid = (lo + hi) >> 1;
                    if (s_p[mid] <= g) lo = mid; else hi = mid;
                }
                rv = g_rowlist[(e * NRB + lo) * ROWS_PB + (g - s_p[lo])];
            }
            rowids[tid] = rv;
        }
        __syncthreads();

        int ar = tid >> 3;                       // A row 0..31
        int rvA = rowids[ar];
        int ridA = (rvA < 0) ? 0 : (rvA & 0x3FFFFFFF);
        const __half* xh = g_xh + (size_t)ridA * II;

        // ---- Interleaved commits: A0,(B1),A1,(B2),A2,(B3),A3 ----
#pragma unroll
        for (int c = 0; c < 4; c++) {
            cp16(sb + SM_A + c * ASEC + ar * 144 + ac * 16, xh + c * 64 + ac * 8);
            asm volatile("cp.async.commit_group;" ::: "memory");
            if (first_tile && c < 3) loadB(c + 1);
        }

        float dp[2][2][2][4];     // [parity][mt][nt][q]
#pragma unroll
        for (int pa = 0; pa < 2; pa++)
#pragma unroll
            for (int mt = 0; mt < 2; mt++)
#pragma unroll
                for (int nt = 0; nt < 2; nt++)
#pragma unroll
                    for (int q = 0; q < 4; q++) dp[pa][mt][nt][q] = 0.f;

#pragma unroll
        for (int c = 0; c < 4; c++) {
            // Gate: first tile pending {6,4,2,0}; later tiles {3,2,1,0}.
            if (first_tile) {
                if (c == 0)      asm volatile("cp.async.wait_group 6;" ::: "memory");
                else if (c == 1) asm volatile("cp.async.wait_group 4;" ::: "memory");
                else if (c == 2) asm volatile("cp.async.wait_group 2;" ::: "memory");
                else             asm volatile("cp.async.wait_group 0;" ::: "memory");
            } else {
                if (c == 0)      asm volatile("cp.async.wait_group 3;" ::: "memory");
                else if (c == 1) asm volatile("cp.async.wait_group 2;" ::: "memory");
                else if (c == 2) asm volatile("cp.async.wait_group 1;" ::: "memory");
                else             asm volatile("cp.async.wait_group 0;" ::: "memory");
            }
            __syncthreads();

            uint32_t abase = sb + SM_A + c * ASEC;
            uint32_t aAh0 = abase + aoff;                    // A rows 0-15
            uint32_t aAh1 = abase + 2304 + aoff;             // A rows 16-31
            uint32_t aB   = sb + SM_B + c * BSEC + boff;     // B (warp's 16 n-rows)

            // Register double-buffered ks pipeline (3 LDSM4 per ks)
            uint32_t fh[2][2][4], fb[2][4];
            LDSM4(fh[0][0], aAh0);
            LDSM4(fh[0][1], aAh1);
            LDSM4(fb[0], aB);

#pragma unroll
            for (int ks = 0; ks < 4; ks++) {
                int cur = ks & 1, nxt = cur ^ 1;
                if (ks < 3) {
                    uint32_t o = (uint32_t)(ks + 1) * 32u;
                    LDSM4(fh[nxt][0], aAh0 + o);
                    LDSM4(fh[nxt][1], aAh1 + o);
                    LDSM4(fb[nxt], aB + o);
                }
                float (*dd)[2][4] = dp[ks & 1];   // ks-parity accumulator set
#pragma unroll
                for (int nt = 0; nt < 2; nt++)
#pragma unroll
                    for (int mt = 0; mt < 2; mt++)
                        MMAF16(dd[mt][nt], fh[cur][mt], fb[cur] + nt * 2);
            }
            // no trailing barrier: smem read-only until the tile loop wraps
        }
        first_tile = false;

        // Epilogue: combine parity sets, scatter D fragments
#pragma unroll
        for (int mt = 0; mt < 2; mt++) {
#pragma unroll
            for (int h = 0; h < 2; h++) {
                int rr = mt * 16 + gid + h * 8;
                int rv = rowids[rr];
                if (rv < 0) continue;
                int rid = rv & 0x3FFFFFFF;
                bool multi = (rv & 0x40000000) != 0;
                float* yp = y + (size_t)rid * OO + half * 128 + wid * 16 + 2 * tig;
                if (multi) {
#pragma unroll
                    for (int nt = 0; nt < 2; nt++) {
                        atomicAdd(&yp[nt * 8],
                                  dp[0][mt][nt][h * 2 + 0] + dp[1][mt][nt][h * 2 + 0]);
                        atomicAdd(&yp[nt * 8 + 1],
                                  dp[0][mt][nt][h * 2 + 1] + dp[1][mt][nt][h * 2 + 1]);
                    }
                } else {
#pragma unroll
                    for (int nt = 0; nt < 2; nt++)
                        *reinterpret_cast<float2*>(&yp[nt * 8]) = make_float2(
                            dp[0][mt][nt][h * 2 + 0] + dp[1][mt][nt][h * 2 + 0],
                            dp[0][mt][nt][h * 2 + 1] + dp[1][mt][nt][h * 2 + 1]);
                }
            }
        }
        __syncthreads();    // all reads of rowids/A sections done before next tile rewrites
    }
}

extern "C" void kernel_launch(void* const* d_in, const int* in_sizes, int n_in,
                              void* d_out, int out_size) {
    const float* x  = (const float*)d_in[0];
    const float* W  = (const float*)d_in[1];
    const float* Wp = (const float*)d_in[2];
    const float* bp = (const float*)d_in[3];
    float* y = (float*)d_out;

    cudaFuncSetAttribute(gemm_kernel, cudaFuncAttributeMaxDynamicSharedMemorySize, SMEM_GEMM);
    prep_kernel<<<NRB, 256>>>(x, W, Wp, bp, y);
    gemm_kernel<<<dim3(16, TSTRIDE), 256, SMEM_GEMM>>>(y);
}